// round 14
// baseline (speedup 1.0000x reference)
#include <cuda_runtime.h>
#include <cstdint>

#define N_NODES 8192
#define E_EDGES 262144
#define IN_DIM  512
#define HID_DIM 256
#define Z_DIM   64

// Scratch (device globals: allocation-free)
__device__ float g_h0[N_NODES * HID_DIM];   // x @ W1
__device__ float g_h [N_NODES * HID_DIM];   // relu(spmm(h0))
__device__ float g_p [N_NODES * Z_DIM];     // h @ W2
__device__ int   g_rowptr[N_NODES + 1];

// ---------------------------------------------------------------------------
// tf32 helpers
// ---------------------------------------------------------------------------
__device__ __forceinline__ uint32_t f2tf32(float f) {
    uint32_t r; asm("cvt.rna.tf32.f32 %0, %1;" : "=r"(r) : "f"(f)); return r;
}

__device__ __forceinline__ void mma_tf32(float d[4],
    uint32_t a0, uint32_t a1, uint32_t a2, uint32_t a3,
    uint32_t b0, uint32_t b1)
{
    asm("mma.sync.aligned.m16n8k8.row.col.f32.tf32.tf32.f32 "
        "{%0,%1,%2,%3}, {%4,%5,%6,%7}, {%8,%9}, {%0,%1,%2,%3};"
        : "+f"(d[0]), "+f"(d[1]), "+f"(d[2]), "+f"(d[3])
        : "r"(a0), "r"(a1), "r"(a2), "r"(a3), "r"(b0), "r"(b1));
}

// ---------------------------------------------------------------------------
__global__ void noop_kernel() {}

// ---------------------------------------------------------------------------
// CSR row pointer from sorted edge_row
// ---------------------------------------------------------------------------
__global__ void rowptr_kernel(const int* __restrict__ er) {
    int i = blockIdx.x * blockDim.x + threadIdx.x;
    if (i > N_NODES) return;
    int lo = 0, hi = E_EDGES;
    while (lo < hi) {
        int mid = (lo + hi) >> 1;
        if (er[mid] < i) lo = mid + 1; else hi = mid;
    }
    g_rowptr[i] = lo;
}

// ---------------------------------------------------------------------------
// tf32 tensor-core GEMM (R6/R10-proven: contiguous STS.128 staging, GS=BK+4)
// ---------------------------------------------------------------------------
#define GS 36

template<int BM, int BN, int WM, int WN>
__global__ __launch_bounds__(256) void gemm_tc(
    const float* __restrict__ A, const float* __restrict__ B,
    float* __restrict__ C, int M, int K, int N)
{
    constexpr int BK = 32;
    constexpr int MI = WM / 16;
    constexpr int NI = WN / 8;
    constexpr int NWN = BN / WN;
    constexpr int LA = BM * (BK / 4) / 256;
    constexpr int LB = BK * (BN / 4) / 256;

    extern __shared__ uint32_t gsm[];
    uint32_t* As = gsm;
    uint32_t* Bs = gsm + BM * GS;

    const int tid  = threadIdx.x;
    const int lane = tid & 31;
    const int warp = tid >> 5;
    const int gid  = lane >> 2;
    const int tig  = lane & 3;
    const int wm   = (warp / NWN) * WM;
    const int wn   = (warp % NWN) * WN;
    const int mbase = blockIdx.y * BM;
    const int nbase = blockIdx.x * BN;

    float acc[MI][NI][4] = {};
    float4 apf[LA], bpf[LB];

    #pragma unroll
    for (int u = 0; u < LA; ++u) {
        int idx = tid + u * 256;
        int r = idx / (BK / 4), c4 = (idx % (BK / 4)) * 4;
        apf[u] = *(const float4*)&A[(size_t)(mbase + r) * K + c4];
    }
    #pragma unroll
    for (int u = 0; u < LB; ++u) {
        int idx = tid + u * 256;
        int k = idx / (BN / 4), n4 = (idx % (BN / 4)) * 4;
        bpf[u] = *(const float4*)&B[(size_t)k * N + nbase + n4];
    }

    for (int kk = 0; kk < K; kk += BK) {
        #pragma unroll
        for (int u = 0; u < LA; ++u) {
            int idx = tid + u * 256;
            int r = idx / (BK / 4), c4 = (idx % (BK / 4)) * 4;
            uint4 t = { f2tf32(apf[u].x), f2tf32(apf[u].y),
                        f2tf32(apf[u].z), f2tf32(apf[u].w) };
            *(uint4*)&As[r * GS + c4] = t;
        }
        #pragma unroll
        for (int u = 0; u < LB; ++u) {
            int idx = tid + u * 256;
            int k = idx / (BN / 4), n4 = (idx % (BN / 4)) * 4;
            Bs[(n4 + 0) * GS + k] = f2tf32(bpf[u].x);
            Bs[(n4 + 1) * GS + k] = f2tf32(bpf[u].y);
            Bs[(n4 + 2) * GS + k] = f2tf32(bpf[u].z);
            Bs[(n4 + 3) * GS + k] = f2tf32(bpf[u].w);
        }
        __syncthreads();

        if (kk + BK < K) {
            #pragma unroll
            for (int u = 0; u < LA; ++u) {
                int idx = tid + u * 256;
                int r = idx / (BK / 4), c4 = (idx % (BK / 4)) * 4;
                apf[u] = *(const float4*)&A[(size_t)(mbase + r) * K + kk + BK + c4];
            }
            #pragma unroll
            for (int u = 0; u < LB; ++u) {
                int idx = tid + u * 256;
                int k = idx / (BN / 4), n4 = (idx % (BN / 4)) * 4;
                bpf[u] = *(const float4*)&B[(size_t)(kk + BK + k) * N + nbase + n4];
            }
        }

        #pragma unroll
        for (int kb = 0; kb < 4; ++kb) {
            const int kc = kb * 8;
            uint32_t a[MI][4], b[NI][2];
            #pragma unroll
            for (int mi = 0; mi < MI; ++mi) {
                int base = (wm + mi * 16 + gid) * GS + kc + tig;
                a[mi][0] = As[base];
                a[mi][1] = As[base + 8 * GS];
                a[mi][2] = As[base + 4];
                a[mi][3] = As[base + 8 * GS + 4];
            }
            #pragma unroll
            for (int ni = 0; ni < NI; ++ni) {
                int base = (wn + ni * 8 + gid) * GS + kc + tig;
                b[ni][0] = Bs[base];
                b[ni][1] = Bs[base + 4];
            }
            #pragma unroll
            for (int mi = 0; mi < MI; ++mi)
                #pragma unroll
                for (int ni = 0; ni < NI; ++ni)
                    mma_tf32(acc[mi][ni], a[mi][0], a[mi][1], a[mi][2], a[mi][3],
                             b[ni][0], b[ni][1]);
        }
        __syncthreads();
    }

    #pragma unroll
    for (int mi = 0; mi < MI; ++mi) {
        #pragma unroll
        for (int ni = 0; ni < NI; ++ni) {
            int col = nbase + wn + ni * 8 + 2 * tig;
            size_t r0 = (size_t)(mbase + wm + mi * 16 + gid) * N;
            size_t r1 = r0 + 8 * (size_t)N;
            *(float2*)&C[r0 + col] = make_float2(acc[mi][ni][0], acc[mi][ni][1]);
            *(float2*)&C[r1 + col] = make_float2(acc[mi][ni][2], acc[mi][ni][3]);
        }
    }
}

// ---------------------------------------------------------------------------
// SpMM, float4 lanes, 4-edge unroll (R6-proven)
// ---------------------------------------------------------------------------
template<int D, bool RELU>
__global__ void spmm_kernel(const float* __restrict__ hin,
                            const int*   __restrict__ col,
                            const float* __restrict__ wgt,
                            float* __restrict__ hout)
{
    int row = blockIdx.x * blockDim.y + threadIdx.y;
    int d4 = threadIdx.x * 4;
    int s = g_rowptr[row];
    int e = g_rowptr[row + 1];
    float ax = 0.f, ay = 0.f, az = 0.f, aw = 0.f;
    int i = s;
    for (; i + 4 <= e; i += 4) {
        int   c0 = col[i+0], c1 = col[i+1], c2 = col[i+2], c3 = col[i+3];
        float w0 = wgt[i+0], w1 = wgt[i+1], w2 = wgt[i+2], w3 = wgt[i+3];
        float4 v0 = *(const float4*)&hin[(size_t)c0 * D + d4];
        float4 v1 = *(const float4*)&hin[(size_t)c1 * D + d4];
        float4 v2 = *(const float4*)&hin[(size_t)c2 * D + d4];
        float4 v3 = *(const float4*)&hin[(size_t)c3 * D + d4];
        ax += w0*v0.x + w1*v1.x + w2*v2.x + w3*v3.x;
        ay += w0*v0.y + w1*v1.y + w2*v2.y + w3*v3.y;
        az += w0*v0.z + w1*v1.z + w2*v2.z + w3*v3.z;
        aw += w0*v0.w + w1*v1.w + w2*v2.w + w3*v3.w;
    }
    for (; i < e; ++i) {
        float w = wgt[i];
        float4 v = *(const float4*)&hin[(size_t)col[i] * D + d4];
        ax += w*v.x; ay += w*v.y; az += w*v.z; aw += w*v.w;
    }
    if (RELU) {
        ax = fmaxf(ax, 0.f); ay = fmaxf(ay, 0.f);
        az = fmaxf(az, 0.f); aw = fmaxf(aw, 0.f);
    }
    *(float4*)&hout[(size_t)row * D + d4] = make_float4(ax, ay, az, aw);
}

// ---------------------------------------------------------------------------
// recon = Z @ Z^T, tf32 TC, 64x64 tiles for HIGH OCCUPANCY:
// acc 16 regs/thread, smem 34.8KB -> ~4 blocks/SM (vs 2 at 128x128).
// 8 warps in 2(m) x 4(n) grid, warp tile 32x16. Direct tile from fragments;
// mirror tile via rot-swizzle smem bounce (both R6-proven patterns).
// ---------------------------------------------------------------------------
#define ZT4  64
#define TS   68
#define ZLD4 68

__global__ __launch_bounds__(256) void zzt_tc_kernel(
    const float* __restrict__ Z, float* __restrict__ C)
{
    extern __shared__ uint32_t smu[];
    uint32_t* As = smu;                  // [64][TS]
    uint32_t* Bs = smu + ZT4 * TS;       // [64][TS]

    const int l = blockIdx.x;
    int by = (int)((sqrtf(8.0f * (float)l + 1.0f) - 1.0f) * 0.5f);
    while ((by + 1) * (by + 2) / 2 <= l) ++by;
    while (by * (by + 1) / 2 > l) --by;
    const int bx = l - by * (by + 1) / 2;

    const int tid  = threadIdx.x;
    const int lane = tid & 31;
    const int warp = tid >> 5;
    const int gid  = lane >> 2;
    const int tig  = lane & 3;
    const int wm   = (warp & 1) * 32;    // 2 warps along m
    const int wn   = (warp >> 1) * 16;   // 4 warps along n
    const int rbase = by * ZT4;
    const int cbase = bx * ZT4;

    // stage both operand tiles: 64 rows x 64 k, 4 float4 per thread per tile
    #pragma unroll
    for (int u = 0; u < 4; ++u) {
        int idx = tid + u * 256;             // 0..1023
        int r = idx >> 4, c4 = (idx & 15) << 2;
        float4 va = *(const float4*)&Z[(size_t)(rbase + r) * Z_DIM + c4];
        uint4 ta = { f2tf32(va.x), f2tf32(va.y), f2tf32(va.z), f2tf32(va.w) };
        *(uint4*)&As[r * TS + c4] = ta;
        float4 vb = *(const float4*)&Z[(size_t)(cbase + r) * Z_DIM + c4];
        uint4 tb = { f2tf32(vb.x), f2tf32(vb.y), f2tf32(vb.z), f2tf32(vb.w) };
        *(uint4*)&Bs[r * TS + c4] = tb;
    }
    __syncthreads();

    float acc[2][2][4] = {};

    #pragma unroll
    for (int kb = 0; kb < 8; ++kb) {
        const int k0 = kb * 8;
        uint32_t a[2][4], b[2][2];
        #pragma unroll
        for (int mi = 0; mi < 2; ++mi) {
            int base = (wm + mi * 16 + gid) * TS + k0 + tig;
            a[mi][0] = As[base];
            a[mi][1] = As[base + 8 * TS];
            a[mi][2] = As[base + 4];
            a[mi][3] = As[base + 8 * TS + 4];
        }
        #pragma unroll
        for (int ni = 0; ni < 2; ++ni) {
            int base = (wn + ni * 8 + gid) * TS + k0 + tig;
            b[ni][0] = Bs[base];
            b[ni][1] = Bs[base + 4];
        }
        #pragma unroll
        for (int mi = 0; mi < 2; ++mi)
            #pragma unroll
            for (int ni = 0; ni < 2; ++ni)
                mma_tf32(acc[mi][ni], a[mi][0], a[mi][1], a[mi][2], a[mi][3],
                         b[ni][0], b[ni][1]);
    }

    // direct (lower-triangle) tile straight from fragments
    #pragma unroll
    for (int mi = 0; mi < 2; ++mi) {
        #pragma unroll
        for (int ni = 0; ni < 2; ++ni) {
            int c = cbase + wn + ni * 8 + 2 * tig;
            size_t r0 = (size_t)(rbase + wm + mi * 16 + gid) * N_NODES;
            size_t r1 = r0 + 8 * N_NODES;
            *(float2*)&C[r0 + c] = make_float2(acc[mi][ni][0], acc[mi][ni][1]);
            *(float2*)&C[r1 + c] = make_float2(acc[mi][ni][2], acc[mi][ni][3]);
        }
    }

    if (bx == by) return;

    // mirror tile via rot-swizzle smem bounce (T = 64 x ZLD4 floats)
    __syncthreads();
    float* T = (float*)smu;
    #pragma unroll
    for (int mi = 0; mi < 2; ++mi) {
        #pragma unroll
        for (int ni = 0; ni < 2; ++ni) {
            #pragma unroll
            for (int q = 0; q < 4; ++q) {
                int r = wm + mi * 16 + gid + (q >> 1) * 8;   // 0..63
                int c = wn + ni * 8 + 2 * tig + (q & 1);     // 0..63
                T[c * ZLD4 + ((r + (c & 56)) & 63)] = acc[mi][ni][q];
            }
        }
    }
    __syncthreads();

    // coalesced mirror writes: 4 threads per row, 16 floats each
    {
        const int a  = tid >> 2;            // 0..63 (mirror local row)
        const int qt = (tid & 3) * 16;      // quarter-row base
        const int rot = a & 56;
        #pragma unroll
        for (int j = 0; j < 4; ++j) {
            int b = qt + j * 4;
            float4 v = *(const float4*)&T[a * ZLD4 + ((b + rot) & 63)];
            *(float4*)&C[(size_t)(cbase + a) * N_NODES + rbase + b] = v;
        }
    }
}

// ---------------------------------------------------------------------------
extern "C" void kernel_launch(void* const* d_in, const int* in_sizes, int n_in,
                              void* d_out, int out_size)
{
    const float* x    = (const float*)d_in[0];
    const float* w1   = (const float*)d_in[1];
    const float* w2   = (const float*)d_in[2];
    const int*   erow = (const int*)  d_in[3];
    const int*   ecol = (const int*)  d_in[4];
    const float* ew   = (const float*)d_in[5];

    float* out   = (float*)d_out;
    float* recon = out;                                   // [N, N]
    float* z     = out + (size_t)N_NODES * N_NODES;       // [N, Z_DIM]

    float *h0, *h, *p;
    cudaGetSymbolAddress((void**)&h0, g_h0);
    cudaGetSymbolAddress((void**)&h,  g_h);
    cudaGetSymbolAddress((void**)&p,  g_p);

    // 0. two no-ops: ncu's fixed 4th-launch capture lands on gemm1
    noop_kernel<<<1, 32>>>();
    noop_kernel<<<1, 32>>>();

    // 1. CSR row pointers
    rowptr_kernel<<<(N_NODES + 256) / 256, 256>>>(erow);

    // 2. h0 = x @ W1  [8192 x 256] — R10 config (no split-K)
    {
        const int smem = (128 + 128) * GS * (int)sizeof(uint32_t);   // 36864
        dim3 g(HID_DIM / 128, N_NODES / 128);                        // (2, 64)
        gemm_tc<128, 128, 64, 32><<<g, 256, smem>>>(x, w1, h0, N_NODES, IN_DIM, HID_DIM);
    }

    // 3. h = relu(spmm(h0))
    spmm_kernel<HID_DIM, true><<<N_NODES / 4, dim3(HID_DIM / 4, 4)>>>(h0, ecol, ew, h);

    // 4. p = h @ W2  [8192 x 64] — measured-best 64x64
    {
        const int smem = (64 + 64) * GS * (int)sizeof(uint32_t);     // 18432
        dim3 g(Z_DIM / 64, N_NODES / 64);                            // (1, 128)
        gemm_tc<64, 64, 32, 16><<<g, 256, smem>>>(h, w2, p, N_NODES, HID_DIM, Z_DIM);
    }

    // 5. z = spmm(p) -> output tail
    spmm_kernel<Z_DIM, false><<<N_NODES / 16, dim3(Z_DIM / 4, 16)>>>(p, ecol, ew, z);

    // 6. recon = z @ z^T, 64x64 high-occupancy tiles
    const int n_tiles = N_NODES / ZT4;                      // 128
    const int n_blocks = n_tiles * (n_tiles + 1) / 2;       // 8256
    const int zzt_smem = 2 * ZT4 * TS * (int)sizeof(uint32_t);   // 34816 B
    cudaFuncSetAttribute(zzt_tc_kernel, cudaFuncAttributeMaxDynamicSharedMemorySize, zzt_smem);
    zzt_tc_kernel<<<n_blocks, 256, zzt_smem>>>(z, recon);
}

// round 15
// speedup vs baseline: 1.0321x; 1.0321x over previous
#include <cuda_runtime.h>
#include <cstdint>

#define N_NODES 8192
#define E_EDGES 262144
#define IN_DIM  512
#define HID_DIM 256
#define Z_DIM   64

// Scratch (device globals: allocation-free)
__device__ float g_h0[N_NODES * HID_DIM];   // x @ W1
__device__ float g_h [N_NODES * HID_DIM];   // relu(spmm(h0))
__device__ float g_p [N_NODES * Z_DIM];     // h @ W2
__device__ int   g_rowptr[N_NODES + 1];

// ---------------------------------------------------------------------------
// tf32 helpers
// ---------------------------------------------------------------------------
__device__ __forceinline__ uint32_t f2tf32(float f) {
    uint32_t r; asm("cvt.rna.tf32.f32 %0, %1;" : "=r"(r) : "f"(f)); return r;
}

__device__ __forceinline__ void mma_tf32(float d[4],
    uint32_t a0, uint32_t a1, uint32_t a2, uint32_t a3,
    uint32_t b0, uint32_t b1)
{
    asm("mma.sync.aligned.m16n8k8.row.col.f32.tf32.tf32.f32 "
        "{%0,%1,%2,%3}, {%4,%5,%6,%7}, {%8,%9}, {%0,%1,%2,%3};"
        : "+f"(d[0]), "+f"(d[1]), "+f"(d[2]), "+f"(d[3])
        : "r"(a0), "r"(a1), "r"(a2), "r"(a3), "r"(b0), "r"(b1));
}

// ---------------------------------------------------------------------------
__global__ void noop_kernel() {}

// ---------------------------------------------------------------------------
// CSR row pointer from sorted edge_row
// ---------------------------------------------------------------------------
__global__ void rowptr_kernel(const int* __restrict__ er) {
    int i = blockIdx.x * blockDim.x + threadIdx.x;
    if (i > N_NODES) return;
    int lo = 0, hi = E_EDGES;
    while (lo < hi) {
        int mid = (lo + hi) >> 1;
        if (er[mid] < i) lo = mid + 1; else hi = mid;
    }
    g_rowptr[i] = lo;
}

// ---------------------------------------------------------------------------
// tf32 tensor-core GEMM (contiguous STS.128 staging, GS=BK+4), NT threads.
// ---------------------------------------------------------------------------
#define GS 36

template<int BM, int BN, int WM, int WN, int NT>
__global__ __launch_bounds__(NT) void gemm_tc(
    const float* __restrict__ A, const float* __restrict__ B,
    float* __restrict__ C, int M, int K, int N)
{
    constexpr int BK = 32;
    constexpr int MI = WM / 16;
    constexpr int NI = WN / 8;
    constexpr int NWN = BN / WN;
    constexpr int LA = BM * (BK / 4) / NT;
    constexpr int LB = BK * (BN / 4) / NT;

    extern __shared__ uint32_t gsm[];
    uint32_t* As = gsm;
    uint32_t* Bs = gsm + BM * GS;

    const int tid  = threadIdx.x;
    const int lane = tid & 31;
    const int warp = tid >> 5;
    const int gid  = lane >> 2;
    const int tig  = lane & 3;
    const int wm   = (warp / NWN) * WM;
    const int wn   = (warp % NWN) * WN;
    const int mbase = blockIdx.y * BM;
    const int nbase = blockIdx.x * BN;

    float acc[MI][NI][4] = {};
    float4 apf[LA], bpf[LB];

    #pragma unroll
    for (int u = 0; u < LA; ++u) {
        int idx = tid + u * NT;
        int r = idx / (BK / 4), c4 = (idx % (BK / 4)) * 4;
        apf[u] = *(const float4*)&A[(size_t)(mbase + r) * K + c4];
    }
    #pragma unroll
    for (int u = 0; u < LB; ++u) {
        int idx = tid + u * NT;
        int k = idx / (BN / 4), n4 = (idx % (BN / 4)) * 4;
        bpf[u] = *(const float4*)&B[(size_t)k * N + nbase + n4];
    }

    for (int kk = 0; kk < K; kk += BK) {
        #pragma unroll
        for (int u = 0; u < LA; ++u) {
            int idx = tid + u * NT;
            int r = idx / (BK / 4), c4 = (idx % (BK / 4)) * 4;
            uint4 t = { f2tf32(apf[u].x), f2tf32(apf[u].y),
                        f2tf32(apf[u].z), f2tf32(apf[u].w) };
            *(uint4*)&As[r * GS + c4] = t;
        }
        #pragma unroll
        for (int u = 0; u < LB; ++u) {
            int idx = tid + u * NT;
            int k = idx / (BN / 4), n4 = (idx % (BN / 4)) * 4;
            Bs[(n4 + 0) * GS + k] = f2tf32(bpf[u].x);
            Bs[(n4 + 1) * GS + k] = f2tf32(bpf[u].y);
            Bs[(n4 + 2) * GS + k] = f2tf32(bpf[u].z);
            Bs[(n4 + 3) * GS + k] = f2tf32(bpf[u].w);
        }
        __syncthreads();

        if (kk + BK < K) {
            #pragma unroll
            for (int u = 0; u < LA; ++u) {
                int idx = tid + u * NT;
                int r = idx / (BK / 4), c4 = (idx % (BK / 4)) * 4;
                apf[u] = *(const float4*)&A[(size_t)(mbase + r) * K + kk + BK + c4];
            }
            #pragma unroll
            for (int u = 0; u < LB; ++u) {
                int idx = tid + u * NT;
                int k = idx / (BN / 4), n4 = (idx % (BN / 4)) * 4;
                bpf[u] = *(const float4*)&B[(size_t)(kk + BK + k) * N + nbase + n4];
            }
        }

        #pragma unroll
        for (int kb = 0; kb < 4; ++kb) {
            const int kc = kb * 8;
            uint32_t a[MI][4], b[NI][2];
            #pragma unroll
            for (int mi = 0; mi < MI; ++mi) {
                int base = (wm + mi * 16 + gid) * GS + kc + tig;
                a[mi][0] = As[base];
                a[mi][1] = As[base + 8 * GS];
                a[mi][2] = As[base + 4];
                a[mi][3] = As[base + 8 * GS + 4];
            }
            #pragma unroll
            for (int ni = 0; ni < NI; ++ni) {
                int base = (wn + ni * 8 + gid) * GS + kc + tig;
                b[ni][0] = Bs[base];
                b[ni][1] = Bs[base + 4];
            }
            #pragma unroll
            for (int mi = 0; mi < MI; ++mi)
                #pragma unroll
                for (int ni = 0; ni < NI; ++ni)
                    mma_tf32(acc[mi][ni], a[mi][0], a[mi][1], a[mi][2], a[mi][3],
                             b[ni][0], b[ni][1]);
        }
        __syncthreads();
    }

    #pragma unroll
    for (int mi = 0; mi < MI; ++mi) {
        #pragma unroll
        for (int ni = 0; ni < NI; ++ni) {
            int col = nbase + wn + ni * 8 + 2 * tig;
            size_t r0 = (size_t)(mbase + wm + mi * 16 + gid) * N;
            size_t r1 = r0 + 8 * (size_t)N;
            *(float2*)&C[r0 + col] = make_float2(acc[mi][ni][0], acc[mi][ni][1]);
            *(float2*)&C[r1 + col] = make_float2(acc[mi][ni][2], acc[mi][ni][3]);
        }
    }
}

// ---------------------------------------------------------------------------
// SpMM, float4 lanes, 4-edge unroll (R6-proven)
// ---------------------------------------------------------------------------
template<int D, bool RELU>
__global__ void spmm_kernel(const float* __restrict__ hin,
                            const int*   __restrict__ col,
                            const float* __restrict__ wgt,
                            float* __restrict__ hout)
{
    int row = blockIdx.x * blockDim.y + threadIdx.y;
    int d4 = threadIdx.x * 4;
    int s = g_rowptr[row];
    int e = g_rowptr[row + 1];
    float ax = 0.f, ay = 0.f, az = 0.f, aw = 0.f;
    int i = s;
    for (; i + 4 <= e; i += 4) {
        int   c0 = col[i+0], c1 = col[i+1], c2 = col[i+2], c3 = col[i+3];
        float w0 = wgt[i+0], w1 = wgt[i+1], w2 = wgt[i+2], w3 = wgt[i+3];
        float4 v0 = *(const float4*)&hin[(size_t)c0 * D + d4];
        float4 v1 = *(const float4*)&hin[(size_t)c1 * D + d4];
        float4 v2 = *(const float4*)&hin[(size_t)c2 * D + d4];
        float4 v3 = *(const float4*)&hin[(size_t)c3 * D + d4];
        ax += w0*v0.x + w1*v1.x + w2*v2.x + w3*v3.x;
        ay += w0*v0.y + w1*v1.y + w2*v2.y + w3*v3.y;
        az += w0*v0.z + w1*v1.z + w2*v2.z + w3*v3.z;
        aw += w0*v0.w + w1*v1.w + w2*v2.w + w3*v3.w;
    }
    for (; i < e; ++i) {
        float w = wgt[i];
        float4 v = *(const float4*)&hin[(size_t)col[i] * D + d4];
        ax += w*v.x; ay += w*v.y; az += w*v.z; aw += w*v.w;
    }
    if (RELU) {
        ax = fmaxf(ax, 0.f); ay = fmaxf(ay, 0.f);
        az = fmaxf(az, 0.f); aw = fmaxf(aw, 0.f);
    }
    *(float4*)&hout[(size_t)row * D + d4] = make_float4(ax, ay, az, aw);
}

// ---------------------------------------------------------------------------
// recon = Z @ Z^T via tf32 tensor cores — EXACT R6 version (best measured).
// ---------------------------------------------------------------------------
#define ZT     128
#define TS     68
#define ZLD    132

__global__ __launch_bounds__(256) void zzt_tc_kernel(
    const float* __restrict__ Z, float* __restrict__ C)
{
    extern __shared__ uint32_t smu[];
    uint32_t* As = smu;
    uint32_t* Bs = smu + ZT * TS;

    const int l = blockIdx.x;
    int by = (int)((sqrtf(8.0f * (float)l + 1.0f) - 1.0f) * 0.5f);
    while ((by + 1) * (by + 2) / 2 <= l) ++by;
    while (by * (by + 1) / 2 > l) --by;
    const int bx = l - by * (by + 1) / 2;

    const int tid  = threadIdx.x;
    const int lane = tid & 31;
    const int warp = tid >> 5;
    const int gid  = lane >> 2;
    const int tig  = lane & 3;
    const int wm   = (warp & 1) * 64;
    const int wn   = (warp >> 1) * 32;
    const int rbase = by * ZT;
    const int cbase = bx * ZT;

    #pragma unroll
    for (int u = 0; u < 8; ++u) {
        int idx = tid + u * 256;
        int r = idx >> 4, c4 = (idx & 15) << 2;
        float4 va = *(const float4*)&Z[(size_t)(rbase + r) * Z_DIM + c4];
        uint4 ta = { f2tf32(va.x), f2tf32(va.y), f2tf32(va.z), f2tf32(va.w) };
        *(uint4*)&As[r * TS + c4] = ta;
        float4 vb = *(const float4*)&Z[(size_t)(cbase + r) * Z_DIM + c4];
        uint4 tb = { f2tf32(vb.x), f2tf32(vb.y), f2tf32(vb.z), f2tf32(vb.w) };
        *(uint4*)&Bs[r * TS + c4] = tb;
    }
    __syncthreads();

    float acc[4][4][4] = {};

    #pragma unroll
    for (int kb = 0; kb < 8; ++kb) {
        const int k0 = kb * 8;
        uint32_t a[4][4], b[4][2];
        #pragma unroll
        for (int mi = 0; mi < 4; ++mi) {
            int base = (wm + mi * 16 + gid) * TS + k0 + tig;
            a[mi][0] = As[base];
            a[mi][1] = As[base + 8 * TS];
            a[mi][2] = As[base + 4];
            a[mi][3] = As[base + 8 * TS + 4];
        }
        #pragma unroll
        for (int ni = 0; ni < 4; ++ni) {
            int base = (wn + ni * 8 + gid) * TS + k0 + tig;
            b[ni][0] = Bs[base];
            b[ni][1] = Bs[base + 4];
        }
        #pragma unroll
        for (int mi = 0; mi < 4; ++mi)
            #pragma unroll
            for (int ni = 0; ni < 4; ++ni)
                mma_tf32(acc[mi][ni], a[mi][0], a[mi][1], a[mi][2], a[mi][3],
                         b[ni][0], b[ni][1]);
    }

    #pragma unroll
    for (int mi = 0; mi < 4; ++mi) {
        #pragma unroll
        for (int ni = 0; ni < 4; ++ni) {
            int c = cbase + wn + ni * 8 + 2 * tig;
            size_t r0 = (size_t)(rbase + wm + mi * 16 + gid) * N_NODES;
            size_t r1 = r0 + 8 * N_NODES;
            *(float2*)&C[r0 + c] = make_float2(acc[mi][ni][0], acc[mi][ni][1]);
            *(float2*)&C[r1 + c] = make_float2(acc[mi][ni][2], acc[mi][ni][3]);
        }
    }

    if (bx == by) return;

    __syncthreads();
    float* T = (float*)smu;
    #pragma unroll
    for (int mi = 0; mi < 4; ++mi) {
        #pragma unroll
        for (int ni = 0; ni < 4; ++ni) {
            #pragma unroll
            for (int q = 0; q < 4; ++q) {
                int r = wm + mi * 16 + gid + (q >> 1) * 8;
                int c = wn + ni * 8 + 2 * tig + (q & 1);
                T[c * ZLD + ((r + (c & 120)) & 127)] = acc[mi][ni][q];
            }
        }
    }
    __syncthreads();

    const int a  = tid >> 1;
    const int hb = (tid & 1) * 64;
    const int rot = a & 120;
    #pragma unroll
    for (int j = 0; j < 16; ++j) {
        int b = hb + j * 4;
        float4 v = *(const float4*)&T[a * ZLD + ((b + rot) & 127)];
        *(float4*)&C[(size_t)(cbase + a) * N_NODES + rbase + b] = v;
    }
}

// ---------------------------------------------------------------------------
extern "C" void kernel_launch(void* const* d_in, const int* in_sizes, int n_in,
                              void* d_out, int out_size)
{
    const float* x    = (const float*)d_in[0];
    const float* w1   = (const float*)d_in[1];
    const float* w2   = (const float*)d_in[2];
    const int*   erow = (const int*)  d_in[3];
    const int*   ecol = (const int*)  d_in[4];
    const float* ew   = (const float*)d_in[5];

    float* out   = (float*)d_out;
    float* recon = out;                                   // [N, N]
    float* z     = out + (size_t)N_NODES * N_NODES;       // [N, Z_DIM]

    float *h0, *h, *p;
    cudaGetSymbolAddress((void**)&h0, g_h0);
    cudaGetSymbolAddress((void**)&h,  g_h);
    cudaGetSymbolAddress((void**)&p,  g_p);

    // 0. two no-ops: ncu's fixed 4th-launch capture lands on gemm1
    noop_kernel<<<1, 32>>>();
    noop_kernel<<<1, 32>>>();

    // 1. CSR row pointers
    rowptr_kernel<<<(N_NODES + 256) / 256, 256>>>(erow);

    // 2. h0 = x @ W1  [8192 x 256] — 128x128 tile, 512 threads / 16 warps
    //    (warp tile 32x32; doubles latency-hiding warps per SM)
    //    <-- 4th launch: ncu captures this one
    {
        const int smem = (128 + 128) * GS * (int)sizeof(uint32_t);   // 36864
        dim3 g(HID_DIM / 128, N_NODES / 128);                        // (2, 64)
        gemm_tc<128, 128, 32, 32, 512><<<g, 512, smem>>>(x, w1, h0, N_NODES, IN_DIM, HID_DIM);
    }

    // 3. h = relu(spmm(h0))
    spmm_kernel<HID_DIM, true><<<N_NODES / 4, dim3(HID_DIM / 4, 4)>>>(h0, ecol, ew, h);

    // 4. p = h @ W2  [8192 x 64] — measured-best 64x64 / 256t
    {
        const int smem = (64 + 64) * GS * (int)sizeof(uint32_t);     // 18432
        dim3 g(Z_DIM / 64, N_NODES / 64);                            // (1, 128)
        gemm_tc<64, 64, 32, 16, 256><<<g, 256, smem>>>(h, w2, p, N_NODES, HID_DIM, Z_DIM);
    }

    // 5. z = spmm(p) -> output tail
    spmm_kernel<Z_DIM, false><<<N_NODES / 16, dim3(Z_DIM / 4, 16)>>>(p, ecol, ew, z);

    // 6. recon = z @ z^T (exact R6 kernel)
    const int n_tiles = N_NODES / ZT;
    const int n_blocks = n_tiles * (n_tiles + 1) / 2;       // 2080
    const int zzt_smem = 2 * ZT * TS * (int)sizeof(uint32_t);   // 69632 B
    cudaFuncSetAttribute(zzt_tc_kernel, cudaFuncAttributeMaxDynamicSharedMemorySize, zzt_smem);
    zzt_tc_kernel<<<n_blocks, 256, zzt_smem>>>(z, recon);
}

// round 17
// speedup vs baseline: 1.0810x; 1.0474x over previous
#include <cuda_runtime.h>
#include <cstdint>

#define N_NODES 8192
#define E_EDGES 262144
#define IN_DIM  512
#define HID_DIM 256
#define Z_DIM   64

// Scratch (device globals: allocation-free)
__device__ float g_h0[N_NODES * HID_DIM];   // x @ W1
__device__ float g_h [N_NODES * HID_DIM];   // relu(spmm(h0))
__device__ float g_p [N_NODES * Z_DIM];     // h @ W2
__device__ int   g_rowptr[N_NODES + 1];

// ---------------------------------------------------------------------------
// tf32 helpers — cvt.rna REQUIRED (R16 proved truncation fails correctness)
// ---------------------------------------------------------------------------
__device__ __forceinline__ uint32_t f2tf32(float f) {
    uint32_t r; asm("cvt.rna.tf32.f32 %0, %1;" : "=r"(r) : "f"(f)); return r;
}

__device__ __forceinline__ void mma_tf32(float d[4],
    uint32_t a0, uint32_t a1, uint32_t a2, uint32_t a3,
    uint32_t b0, uint32_t b1)
{
    asm("mma.sync.aligned.m16n8k8.row.col.f32.tf32.tf32.f32 "
        "{%0,%1,%2,%3}, {%4,%5,%6,%7}, {%8,%9}, {%0,%1,%2,%3};"
        : "+f"(d[0]), "+f"(d[1]), "+f"(d[2]), "+f"(d[3])
        : "r"(a0), "r"(a1), "r"(a2), "r"(a3), "r"(b0), "r"(b1));
}

// streaming store (write-once data; keep L2 for reads)
__device__ __forceinline__ void stcs4(float* p, float4 v) {
    asm volatile("st.global.cs.v4.f32 [%0], {%1,%2,%3,%4};"
                 :: "l"(p), "f"(v.x), "f"(v.y), "f"(v.z), "f"(v.w) : "memory");
}
__device__ __forceinline__ void stcs2(float* p, float2 v) {
    asm volatile("st.global.cs.v2.f32 [%0], {%1,%2};"
                 :: "l"(p), "f"(v.x), "f"(v.y) : "memory");
}

// ---------------------------------------------------------------------------
__global__ void noop_kernel() {}

// ---------------------------------------------------------------------------
// CSR row pointer from sorted edge_row
// ---------------------------------------------------------------------------
__global__ void rowptr_kernel(const int* __restrict__ er) {
    int i = blockIdx.x * blockDim.x + threadIdx.x;
    if (i > N_NODES) return;
    int lo = 0, hi = E_EDGES;
    while (lo < hi) {
        int mid = (lo + hi) >> 1;
        if (er[mid] < i) lo = mid + 1; else hi = mid;
    }
    g_rowptr[i] = lo;
}

// ---------------------------------------------------------------------------
// tf32 tensor-core GEMM (contiguous STS.128 staging, GS=BK+4), NT threads.
// ---------------------------------------------------------------------------
#define GS 36

template<int BM, int BN, int WM, int WN, int NT>
__global__ __launch_bounds__(NT) void gemm_tc(
    const float* __restrict__ A, const float* __restrict__ B,
    float* __restrict__ C, int M, int K, int N)
{
    constexpr int BK = 32;
    constexpr int MI = WM / 16;
    constexpr int NI = WN / 8;
    constexpr int NWN = BN / WN;
    constexpr int LA = BM * (BK / 4) / NT;
    constexpr int LB = BK * (BN / 4) / NT;

    extern __shared__ uint32_t gsm[];
    uint32_t* As = gsm;
    uint32_t* Bs = gsm + BM * GS;

    const int tid  = threadIdx.x;
    const int lane = tid & 31;
    const int warp = tid >> 5;
    const int gid  = lane >> 2;
    const int tig  = lane & 3;
    const int wm   = (warp / NWN) * WM;
    const int wn   = (warp % NWN) * WN;
    const int mbase = blockIdx.y * BM;
    const int nbase = blockIdx.x * BN;

    float acc[MI][NI][4] = {};
    float4 apf[LA], bpf[LB];

    #pragma unroll
    for (int u = 0; u < LA; ++u) {
        int idx = tid + u * NT;
        int r = idx / (BK / 4), c4 = (idx % (BK / 4)) * 4;
        apf[u] = *(const float4*)&A[(size_t)(mbase + r) * K + c4];
    }
    #pragma unroll
    for (int u = 0; u < LB; ++u) {
        int idx = tid + u * NT;
        int k = idx / (BN / 4), n4 = (idx % (BN / 4)) * 4;
        bpf[u] = *(const float4*)&B[(size_t)k * N + nbase + n4];
    }

    for (int kk = 0; kk < K; kk += BK) {
        #pragma unroll
        for (int u = 0; u < LA; ++u) {
            int idx = tid + u * NT;
            int r = idx / (BK / 4), c4 = (idx % (BK / 4)) * 4;
            uint4 t = { f2tf32(apf[u].x), f2tf32(apf[u].y),
                        f2tf32(apf[u].z), f2tf32(apf[u].w) };
            *(uint4*)&As[r * GS + c4] = t;
        }
        #pragma unroll
        for (int u = 0; u < LB; ++u) {
            int idx = tid + u * NT;
            int k = idx / (BN / 4), n4 = (idx % (BN / 4)) * 4;
            Bs[(n4 + 0) * GS + k] = f2tf32(bpf[u].x);
            Bs[(n4 + 1) * GS + k] = f2tf32(bpf[u].y);
            Bs[(n4 + 2) * GS + k] = f2tf32(bpf[u].z);
            Bs[(n4 + 3) * GS + k] = f2tf32(bpf[u].w);
        }
        __syncthreads();

        if (kk + BK < K) {
            #pragma unroll
            for (int u = 0; u < LA; ++u) {
                int idx = tid + u * NT;
                int r = idx / (BK / 4), c4 = (idx % (BK / 4)) * 4;
                apf[u] = *(const float4*)&A[(size_t)(mbase + r) * K + kk + BK + c4];
            }
            #pragma unroll
            for (int u = 0; u < LB; ++u) {
                int idx = tid + u * NT;
                int k = idx / (BN / 4), n4 = (idx % (BN / 4)) * 4;
                bpf[u] = *(const float4*)&B[(size_t)(kk + BK + k) * N + nbase + n4];
            }
        }

        #pragma unroll
        for (int kb = 0; kb < 4; ++kb) {
            const int kc = kb * 8;
            uint32_t a[MI][4], b[NI][2];
            #pragma unroll
            for (int mi = 0; mi < MI; ++mi) {
                int base = (wm + mi * 16 + gid) * GS + kc + tig;
                a[mi][0] = As[base];
                a[mi][1] = As[base + 8 * GS];
                a[mi][2] = As[base + 4];
                a[mi][3] = As[base + 8 * GS + 4];
            }
            #pragma unroll
            for (int ni = 0; ni < NI; ++ni) {
                int base = (wn + ni * 8 + gid) * GS + kc + tig;
                b[ni][0] = Bs[base];
                b[ni][1] = Bs[base + 4];
            }
            #pragma unroll
            for (int mi = 0; mi < MI; ++mi)
                #pragma unroll
                for (int ni = 0; ni < NI; ++ni)
                    mma_tf32(acc[mi][ni], a[mi][0], a[mi][1], a[mi][2], a[mi][3],
                             b[ni][0], b[ni][1]);
        }
        __syncthreads();
    }

    #pragma unroll
    for (int mi = 0; mi < MI; ++mi) {
        #pragma unroll
        for (int ni = 0; ni < NI; ++ni) {
            int col = nbase + wn + ni * 8 + 2 * tig;
            size_t r0 = (size_t)(mbase + wm + mi * 16 + gid) * N;
            size_t r1 = r0 + 8 * (size_t)N;
            *(float2*)&C[r0 + col] = make_float2(acc[mi][ni][0], acc[mi][ni][1]);
            *(float2*)&C[r1 + col] = make_float2(acc[mi][ni][2], acc[mi][ni][3]);
        }
    }
}

// ---------------------------------------------------------------------------
// SpMM, float4 lanes, 4-edge unroll (R6-proven)
// ---------------------------------------------------------------------------
template<int D, bool RELU>
__global__ void spmm_kernel(const float* __restrict__ hin,
                            const int*   __restrict__ col,
                            const float* __restrict__ wgt,
                            float* __restrict__ hout)
{
    int row = blockIdx.x * blockDim.y + threadIdx.y;
    int d4 = threadIdx.x * 4;
    int s = g_rowptr[row];
    int e = g_rowptr[row + 1];
    float ax = 0.f, ay = 0.f, az = 0.f, aw = 0.f;
    int i = s;
    for (; i + 4 <= e; i += 4) {
        int   c0 = col[i+0], c1 = col[i+1], c2 = col[i+2], c3 = col[i+3];
        float w0 = wgt[i+0], w1 = wgt[i+1], w2 = wgt[i+2], w3 = wgt[i+3];
        float4 v0 = *(const float4*)&hin[(size_t)c0 * D + d4];
        float4 v1 = *(const float4*)&hin[(size_t)c1 * D + d4];
        float4 v2 = *(const float4*)&hin[(size_t)c2 * D + d4];
        float4 v3 = *(const float4*)&hin[(size_t)c3 * D + d4];
        ax += w0*v0.x + w1*v1.x + w2*v2.x + w3*v3.x;
        ay += w0*v0.y + w1*v1.y + w2*v2.y + w3*v3.y;
        az += w0*v0.z + w1*v1.z + w2*v2.z + w3*v3.z;
        aw += w0*v0.w + w1*v1.w + w2*v2.w + w3*v3.w;
    }
    for (; i < e; ++i) {
        float w = wgt[i];
        float4 v = *(const float4*)&hin[(size_t)col[i] * D + d4];
        ax += w*v.x; ay += w*v.y; az += w*v.z; aw += w*v.w;
    }
    if (RELU) {
        ax = fmaxf(ax, 0.f); ay = fmaxf(ay, 0.f);
        az = fmaxf(az, 0.f); aw = fmaxf(aw, 0.f);
    }
    *(float4*)&hout[(size_t)row * D + d4] = make_float4(ax, ay, az, aw);
}

// ---------------------------------------------------------------------------
// recon = Z @ Z^T via tf32 tensor cores — R6 structure + streaming C stores.
// ---------------------------------------------------------------------------
#define ZT     128
#define TS     68
#define ZLD    132

__global__ __launch_bounds__(256) void zzt_tc_kernel(
    const float* __restrict__ Z, float* __restrict__ C)
{
    extern __shared__ uint32_t smu[];
    uint32_t* As = smu;
    uint32_t* Bs = smu + ZT * TS;

    const int l = blockIdx.x;
    int by = (int)((sqrtf(8.0f * (float)l + 1.0f) - 1.0f) * 0.5f);
    while ((by + 1) * (by + 2) / 2 <= l) ++by;
    while (by * (by + 1) / 2 > l) --by;
    const int bx = l - by * (by + 1) / 2;

    const int tid  = threadIdx.x;
    const int lane = tid & 31;
    const int warp = tid >> 5;
    const int gid  = lane >> 2;
    const int tig  = lane & 3;
    const int wm   = (warp & 1) * 64;
    const int wn   = (warp >> 1) * 32;
    const int rbase = by * ZT;
    const int cbase = bx * ZT;

    #pragma unroll
    for (int u = 0; u < 8; ++u) {
        int idx = tid + u * 256;
        int r = idx >> 4, c4 = (idx & 15) << 2;
        float4 va = *(const float4*)&Z[(size_t)(rbase + r) * Z_DIM + c4];
        uint4 ta = { f2tf32(va.x), f2tf32(va.y), f2tf32(va.z), f2tf32(va.w) };
        *(uint4*)&As[r * TS + c4] = ta;
        float4 vb = *(const float4*)&Z[(size_t)(cbase + r) * Z_DIM + c4];
        uint4 tb = { f2tf32(vb.x), f2tf32(vb.y), f2tf32(vb.z), f2tf32(vb.w) };
        *(uint4*)&Bs[r * TS + c4] = tb;
    }
    __syncthreads();

    float acc[4][4][4] = {};

    #pragma unroll
    for (int kb = 0; kb < 8; ++kb) {
        const int k0 = kb * 8;
        uint32_t a[4][4], b[4][2];
        #pragma unroll
        for (int mi = 0; mi < 4; ++mi) {
            int base = (wm + mi * 16 + gid) * TS + k0 + tig;
            a[mi][0] = As[base];
            a[mi][1] = As[base + 8 * TS];
            a[mi][2] = As[base + 4];
            a[mi][3] = As[base + 8 * TS + 4];
        }
        #pragma unroll
        for (int ni = 0; ni < 4; ++ni) {
            int base = (wn + ni * 8 + gid) * TS + k0 + tig;
            b[ni][0] = Bs[base];
            b[ni][1] = Bs[base + 4];
        }
        #pragma unroll
        for (int mi = 0; mi < 4; ++mi)
            #pragma unroll
            for (int ni = 0; ni < 4; ++ni)
                mma_tf32(acc[mi][ni], a[mi][0], a[mi][1], a[mi][2], a[mi][3],
                         b[ni][0], b[ni][1]);
    }

    #pragma unroll
    for (int mi = 0; mi < 4; ++mi) {
        #pragma unroll
        for (int ni = 0; ni < 4; ++ni) {
            int c = cbase + wn + ni * 8 + 2 * tig;
            size_t r0 = (size_t)(rbase + wm + mi * 16 + gid) * N_NODES;
            size_t r1 = r0 + 8 * N_NODES;
            stcs2(&C[r0 + c], make_float2(acc[mi][ni][0], acc[mi][ni][1]));
            stcs2(&C[r1 + c], make_float2(acc[mi][ni][2], acc[mi][ni][3]));
        }
    }

    if (bx == by) return;

    __syncthreads();
    float* T = (float*)smu;
    #pragma unroll
    for (int mi = 0; mi < 4; ++mi) {
        #pragma unroll
        for (int ni = 0; ni < 4; ++ni) {
            #pragma unroll
            for (int q = 0; q < 4; ++q) {
                int r = wm + mi * 16 + gid + (q >> 1) * 8;
                int c = wn + ni * 8 + 2 * tig + (q & 1);
                T[c * ZLD + ((r + (c & 120)) & 127)] = acc[mi][ni][q];
            }
        }
    }
    __syncthreads();

    const int a  = tid >> 1;
    const int hb = (tid & 1) * 64;
    const int rot = a & 120;
    #pragma unroll
    for (int j = 0; j < 16; ++j) {
        int b = hb + j * 4;
        float4 v = *(const float4*)&T[a * ZLD + ((b + rot) & 127)];
        stcs4(&C[(size_t)(cbase + a) * N_NODES + rbase + b], v);
    }
}

// ---------------------------------------------------------------------------
extern "C" void kernel_launch(void* const* d_in, const int* in_sizes, int n_in,
                              void* d_out, int out_size)
{
    const float* x    = (const float*)d_in[0];
    const float* w1   = (const float*)d_in[1];
    const float* w2   = (const float*)d_in[2];
    const int*   erow = (const int*)  d_in[3];
    const int*   ecol = (const int*)  d_in[4];
    const float* ew   = (const float*)d_in[5];

    float* out   = (float*)d_out;
    float* recon = out;                                   // [N, N]
    float* z     = out + (size_t)N_NODES * N_NODES;       // [N, Z_DIM]

    float *h0, *h, *p;
    cudaGetSymbolAddress((void**)&h0, g_h0);
    cudaGetSymbolAddress((void**)&h,  g_h);
    cudaGetSymbolAddress((void**)&p,  g_p);

    // 0. two no-ops: ncu's fixed 4th-launch capture lands on gemm1
    noop_kernel<<<1, 32>>>();
    noop_kernel<<<1, 32>>>();

    // 1. CSR row pointers
    rowptr_kernel<<<(N_NODES + 256) / 256, 256>>>(erow);

    // 2. h0 = x @ W1  [8192 x 256] — R10-proven 128x128 / 256t
    //    <-- 4th launch: ncu captures this one
    {
        const int smem = (128 + 128) * GS * (int)sizeof(uint32_t);   // 36864
        dim3 g(HID_DIM / 128, N_NODES / 128);                        // (2, 64)
        gemm_tc<128, 128, 64, 32, 256><<<g, 256, smem>>>(x, w1, h0, N_NODES, IN_DIM, HID_DIM);
    }

    // 3. h = relu(spmm(h0))
    spmm_kernel<HID_DIM, true><<<N_NODES / 4, dim3(HID_DIM / 4, 4)>>>(h0, ecol, ew, h);

    // 4. p = h @ W2  [8192 x 64] — measured-best 64x64 / 256t
    {
        const int smem = (64 + 64) * GS * (int)sizeof(uint32_t);     // 18432
        dim3 g(Z_DIM / 64, N_NODES / 64);                            // (1, 128)
        gemm_tc<64, 64, 32, 16, 256><<<g, 256, smem>>>(h, w2, p, N_NODES, HID_DIM, Z_DIM);
    }

    // 5. z = spmm(p) -> output tail
    spmm_kernel<Z_DIM, false><<<N_NODES / 16, dim3(Z_DIM / 4, 16)>>>(p, ecol, ew, z);

    // 6. recon = z @ z^T (R6 kernel + streaming stores — the single A/B change)
    const int n_tiles = N_NODES / ZT;
    const int n_blocks = n_tiles * (n_tiles + 1) / 2;       // 2080
    const int zzt_smem = 2 * ZT * TS * (int)sizeof(uint32_t);   // 69632 B
    cudaFuncSetAttribute(zzt_tc_kernel, cudaFuncAttributeMaxDynamicSharedMemorySize, zzt_smem);
    zzt_tc_kernel<<<n_blocks, 256, zzt_smem>>>(z, recon);
}